// round 4
// baseline (speedup 1.0000x reference)
#include <cuda_runtime.h>
#include <math.h>

#define NB 8
#define NL 4096
#define NH 8
#define NM 64
#define NCH 512

typedef unsigned long long u64x;

// ---------------- device scratch ----------------
__device__ ulonglong2 g_ts[4096];            // (cc, ss) packed f32x2 of angle 2*pi*i/4096
__device__ float2 g_F[2 * NB * NM * NCH];    // [tensor][b][mode-pos][ch]
__device__ float2 g_O[NB * NH * 64 * NM];    // [row][mode-pos]: (A, B) pre-scaled

// ---------------- f32x2 helpers ----------------
static __device__ __forceinline__ u64x fma2(u64x a, u64x b, u64x c) {
    u64x d; asm("fma.rn.f32x2 %0,%1,%2,%3;" : "=l"(d) : "l"(a), "l"(b), "l"(c)); return d;
}
static __device__ __forceinline__ u64x add2(u64x a, u64x b) {
    u64x d; asm("add.rn.f32x2 %0,%1,%2;" : "=l"(d) : "l"(a), "l"(b)); return d;
}
#define NEG1X2 0xBF800000BF800000ULL
static __device__ __forceinline__ u64x sub2(u64x a, u64x b) { return fma2(b, NEG1X2, a); }
static __device__ __forceinline__ u64x neg2(u64x a) { return fma2(a, NEG1X2, 0ULL); }
static __device__ __forceinline__ void unpack2(u64x d, float& lo, float& hi) {
    asm("mov.b64 {%0,%1},%2;" : "=f"(lo), "=f"(hi) : "l"(d));
}

// ================= K0: trig table =================
__global__ void k0_init() {
    int i = blockIdx.x * 256 + threadIdx.x;
    if (i < 4096) {
        float s, c;
        sincospif((float)i / 2048.0f, &s, &c);
        u64x cc, ss;
        asm("mov.b64 %0,{%1,%1};" : "=l"(cc) : "f"(c));
        asm("mov.b64 %0,{%1,%1};" : "=l"(ss) : "f"(s));
        g_ts[i] = make_ulonglong2(cc, ss);
    }
}

// ================= K1: forward sparse DFT (radix-4) =================
// X[f] = sum_{t'=0}^{1023} u_{f&3}(t') e^{-i 2pi f t'/4096}
// u0=a+c, u2=a-c (real); u1=bq-i*d, u3=bq+i*d;  a=x0+x2, bq=x0-x2, c=x1+x3, d=x1-x3
// Conventions: accR=Re, accS accumulates so that Im = -accS for all classes.
template<int CLS>
static __device__ __forceinline__ void k1_chunk(
    const u64x* __restrict__ xsd, const ulonglong2* __restrict__ ts2,
    int lane, u64x accR[4], u64x accS[4], int idx[4], const int F[4])
{
#pragma unroll 2
    for (int tt = 0; tt < 32; tt++) {
        u64x x0 = xsd[(0 * 32 + tt) * 32 + lane];
        u64x x1 = xsd[(1 * 32 + tt) * 32 + lane];
        u64x x2 = xsd[(2 * 32 + tt) * 32 + lane];
        u64x x3 = xsd[(3 * 32 + tt) * 32 + lane];
        u64x P, QR = 0, QS = 0;
        if (CLS == 0) {
            P = add2(add2(x0, x2), add2(x1, x3));
        } else if (CLS == 2) {
            P = sub2(add2(x0, x2), add2(x1, x3));
        } else {
            u64x bq = sub2(x0, x2);
            u64x d  = sub2(x1, x3);
            u64x nd = neg2(d);
            P  = bq;
            QR = (CLS == 1) ? nd : d;   // accR += P*cc + QR*ss
            QS = (CLS == 1) ? d  : nd;  // accS += P*ss + QS*cc
        }
#pragma unroll
        for (int k = 0; k < 4; k++) {
            ulonglong2 cs = ts2[idx[k]];
            accR[k] = fma2(P, cs.x, accR[k]);
            accS[k] = fma2(P, cs.y, accS[k]);
            if (CLS & 1) {
                accR[k] = fma2(QR, cs.y, accR[k]);
                accS[k] = fma2(QS, cs.x, accS[k]);
            }
            idx[k] = (idx[k] + F[k]) & 4095;
        }
    }
}

// generic (mixed-class) fallback: plain non-decimated accumulation
static __device__ __forceinline__ void k1_chunk_gen(
    const u64x* __restrict__ xsd, const ulonglong2* __restrict__ ts2,
    int lane, u64x accR[4], u64x accS[4], int chunk, const int F[4])
{
    for (int tt = 0; tt < 32; tt++) {
        int tp = chunk * 32 + tt;
#pragma unroll
        for (int m = 0; m < 4; m++) {
            u64x x = xsd[(m * 32 + tt) * 32 + lane];
            int tg = tp + 1024 * m;
#pragma unroll
            for (int k = 0; k < 4; k++) {
                int id = (F[k] * tg) & 4095;
                ulonglong2 cs = ts2[id];
                accR[k] = fma2(x, cs.x, accR[k]);
                accS[k] = fma2(x, cs.y, accS[k]);
            }
        }
    }
}

#define K1_SMEM (4096 * 16 + 4 * 32 * 64 * 4)   // 64KB trig + 32KB stage = 98304
__global__ void __launch_bounds__(256, 2) k1_forward(const float* __restrict__ qp,
                                                     const float* __restrict__ kp,
                                                     const int* __restrict__ iq,
                                                     const int* __restrict__ ikv) {
    extern __shared__ char sm[];
    ulonglong2* ts2 = (ulonglong2*)sm;
    float* xs = (float*)(ts2 + 4096);            // [4 m][32 t'][64 ch]
    const u64x* xsd = (const u64x*)xs;

    const int ctile = blockIdx.x, b = blockIdx.y;
    const int tensor = blockIdx.z >> 1, mhalf = blockIdx.z & 1;
    const float* src = tensor ? kp : qp;
    const int* idxarr = tensor ? ikv : iq;
    const int tid = threadIdx.x, lane = tid & 31, warp = tid >> 5;

    for (int i = tid; i < 4096; i += 256) ts2[i] = g_ts[i];

    // --- per-warp mode resolution: bucket modes by (F&3), warp gw takes bucketed [4gw,4gw+4) ---
    const unsigned FULL = 0xffffffffu;
    int gw = mhalf * 8 + warp;
    int Flo = idxarr[lane], Fhi = idxarr[lane + 32];
    int clo = Flo & 3, chi = Fhi & 3;
    unsigned mlo[4], mhi[4];
    int off[5]; off[0] = 0;
#pragma unroll
    for (int c = 0; c < 4; c++) {
        mlo[c] = __ballot_sync(FULL, clo == c);
        mhi[c] = __ballot_sync(FULL, chi == c);
    }
#pragma unroll
    for (int c = 0; c < 4; c++) off[c + 1] = off[c] + __popc(mlo[c]) + __popc(mhi[c]);
    unsigned lm = (1u << lane) - 1u;
    int p_lo = off[clo] + __popc(mlo[clo] & lm);
    int p_hi = off[chi] + __popc(mlo[chi]) + __popc(mhi[chi] & lm);
    int mi[4], F[4];
#pragma unroll
    for (int k = 0; k < 4; k++) {
        int tpos = gw * 4 + k;
        unsigned ba = __ballot_sync(FULL, p_lo == tpos);
        unsigned bb = __ballot_sync(FULL, p_hi == tpos);
        int m = ba ? (__ffs(ba) - 1) : (32 + __ffs(bb) - 1);
        mi[k] = m;
        F[k] = __shfl_sync(FULL, (m < 32) ? Flo : Fhi, m & 31);
    }
    int jcls = F[0] & 3;
    bool uni = ((F[1] & 3) == jcls) && ((F[2] & 3) == jcls) && ((F[3] & 3) == jcls);

    u64x accR[4], accS[4]; int idx[4];
#pragma unroll
    for (int k = 0; k < 4; k++) { accR[k] = 0; accS[k] = 0; idx[k] = 0; }

    const float* base = src + (size_t)b * NL * NCH + ctile * 64;

    for (int chunk = 0; chunk < 32; chunk++) {
        __syncthreads();
#pragma unroll
        for (int ii = 0; ii < 8; ii++) {
            int i = ii * 256 + tid;                 // 2048 float4
            int c4 = i & 15, tt = (i >> 4) & 31, m = i >> 9;
            ((float4*)xs)[i] = *(const float4*)(base + (size_t)(chunk * 32 + tt + 1024 * m) * NCH + c4 * 4);
        }
        __syncthreads();
        if (uni) {
            switch (jcls) {
                case 0: k1_chunk<0>(xsd, ts2, lane, accR, accS, idx, F); break;
                case 1: k1_chunk<1>(xsd, ts2, lane, accR, accS, idx, F); break;
                case 2: k1_chunk<2>(xsd, ts2, lane, accR, accS, idx, F); break;
                default: k1_chunk<3>(xsd, ts2, lane, accR, accS, idx, F); break;
            }
        } else {
            k1_chunk_gen(xsd, ts2, lane, accR, accS, chunk, F);
        }
    }

    const int ch = ctile * 64 + lane * 2;
    float2* dst = g_F + ((size_t)(tensor * NB + b) * NM) * NCH;
#pragma unroll
    for (int k = 0; k < 4; k++) {
        float r0, r1, s0, s1;
        unpack2(accR[k], r0, r1);
        unpack2(accS[k], s0, s1);
        dst[(size_t)mi[k] * NCH + ch]     = make_float2(r0, -s0);
        dst[(size_t)mi[k] * NCH + ch + 1] = make_float2(r1, -s1);
    }
}

// ================= K2: per-(b,h) complex middle, x-split =================
#define K2_SMEM ((64*64 + 64*65 + 64*64 + 64*65 + 64*64) * 8)
__global__ void __launch_bounds__(256, 1) k2_middle(const float* __restrict__ w1,
                                                    const float* __restrict__ w2,
                                                    const int* __restrict__ iq) {
    extern __shared__ char sm[];
    float2* sFq  = (float2*)sm;          // [x][e]   64*64
    float2* sFkT = sFq + 64 * 64;        // [e][y]   64*65 (pad)
    float2* sFkY = sFkT + 64 * 65;       // [y][e]   64*64
    float2* sA   = sFkY + 64 * 64;       // [y][x]   64*65 (pad)
    float2* sC   = sA + 64 * 65;         // [e][x]   64*64

    const int bh = blockIdx.x, b = bh >> 3, h = bh & 7;
    const int xh = blockIdx.y;           // x-half
    const int tid = threadIdx.x;

    for (int i = tid; i < 4096; i += 256) {
        int e = i & 63, f = i >> 6;
        float2 vq = g_F[((size_t)(b) * NM + f) * NCH + h * 64 + e];
        float2 vk = g_F[((size_t)(NB + b) * NM + f) * NCH + h * 64 + e];
        sFq[f * 64 + e]  = vq;
        sFkT[e * 65 + f] = vk;
        sFkY[f * 64 + e] = vk;
    }
    __syncthreads();

    // A[x][y] = tanh_c( sum_e Fq[e,x] * Fk[e,y] )
#pragma unroll 1
    for (int p = 0; p < 8; p++) {
        int i = p * 256 + tid, x = xh * 32 + (i >> 6), y = i & 63;
        float re = 0.f, im = 0.f;
#pragma unroll 4
        for (int e = 0; e < 64; e++) {
            float2 a = sFq[x * 64 + e];     // broadcast
            float2 c = sFkT[e * 65 + y];    // consecutive
            re += a.x * c.x - a.y * c.y;
            im += a.x * c.y + a.y * c.x;
        }
        sA[y * 65 + x] = make_float2(tanhf(re), tanhf(im));
    }
    __syncthreads();

    // C[e][x] = sum_y A[x,y] * Fk[e,y]
#pragma unroll 1
    for (int p = 0; p < 8; p++) {
        int i = p * 256 + tid, x = xh * 32 + (i & 31), e = i >> 5;
        float re = 0.f, im = 0.f;
#pragma unroll 4
        for (int y = 0; y < 64; y++) {
            float2 a  = sA[y * 65 + x];     // consecutive
            float2 kv = sFkY[y * 64 + e];   // broadcast
            re += a.x * kv.x - a.y * kv.y;
            im += a.x * kv.y + a.y * kv.x;
        }
        sC[e * 64 + x] = make_float2(re, im);
    }
    __syncthreads();

    // O[o][x] = sum_e C[e,x] * (w1 + i w2)[h,e,o,x]; pre-scale for irfft
#pragma unroll 1
    for (int p = 0; p < 8; p++) {
        int i = p * 256 + tid, x = xh * 32 + (i & 31), o = i >> 5;
        float re = 0.f, im = 0.f;
        size_t wbase = (((size_t)h * 64) * 64 + o) * 64 + x;
#pragma unroll 4
        for (int e = 0; e < 64; e++) {
            float2 c = sC[e * 64 + x];
            float wr = w1[wbase + (size_t)e * 4096];
            float wi = w2[wbase + (size_t)e * 4096];
            re += c.x * wr - c.y * wi;
            im += c.x * wi + c.y * wr;
        }
        int fx = iq[x];
        float s = ((fx == 0) || (fx == NL / 2) ? 1.0f : 2.0f) * 9.313225746154785e-10f; // 2^-30
        int row = (b * 8 + h) * 64 + o;
        g_O[(size_t)row * NM + x] = make_float2(s * re, -s * im);
    }
}

// ================= K3: inverse sparse DFT (radix-4 reconstruction) =================
// out[t'+1024m] = sum_f P_f cos(pi/2 j m) + Q_f sin(pi/2 j m), j=F&3
// P = A cc + B ss ; Q = B cc - A ss   (per t')
#define K3_SMEM (4096*16 + 4096*4*2 + 64*33*4 + 64*8 + 32)
__global__ void __launch_bounds__(256, 2) k3_inverse(float* __restrict__ out,
                                                     const int* __restrict__ iq) {
    extern __shared__ char sm[];
    ulonglong2* ts2 = (ulonglong2*)sm;            // 64KB
    float* sA = (float*)(ts2 + 4096);             // [pos][64 rows]
    float* sB = sA + 4096;
    float* sT = sB + 4096;                        // [64 rows][33]
    int2* sperm = (int2*)(sT + 64 * 33);          // bucketed pos -> (orig pos, freq)
    int* soff = (int*)(sperm + 64);               // class offsets [5]

    const int rt = blockIdx.x;                    // 64 row tiles
    const int tq = blockIdx.y;                    // 4 t' quarters
    const int r0 = rt * 64;
    const int tid = threadIdx.x, lane = tid & 31, warp = tid >> 5;

    for (int i = tid; i < 4096; i += 256) ts2[i] = g_ts[i];
    for (int i = tid; i < 4096; i += 256) {
        int f = i >> 6, rr = i & 63;
        float2 v = g_O[(size_t)(r0 + rr) * NM + f];
        sA[f * 64 + rr] = v.x;
        sB[f * 64 + rr] = v.y;
    }
    if (warp == 0) {
        const unsigned FULL = 0xffffffffu;
        int Flo = iq[lane], Fhi = iq[lane + 32];
        int clo = Flo & 3, chi = Fhi & 3;
        unsigned mlo[4], mhi[4];
        int off[5]; off[0] = 0;
#pragma unroll
        for (int c = 0; c < 4; c++) {
            mlo[c] = __ballot_sync(FULL, clo == c);
            mhi[c] = __ballot_sync(FULL, chi == c);
        }
#pragma unroll
        for (int c = 0; c < 4; c++) off[c + 1] = off[c] + __popc(mlo[c]) + __popc(mhi[c]);
        unsigned lmm = (1u << lane) - 1u;
        int p_lo = off[clo] + __popc(mlo[clo] & lmm);
        int p_hi = off[chi] + __popc(mlo[chi]) + __popc(mhi[chi] & lmm);
        sperm[p_lo] = make_int2(lane, Flo);
        sperm[p_hi] = make_int2(lane + 32, Fhi);
        if (lane < 5) soff[lane] = off[lane];
    }
    __syncthreads();

    const u64x* sAd = (const u64x*)sA;
    const u64x* sBd = (const u64x*)sB;
    const int o0 = soff[0], o1 = soff[1], o2 = soff[2], o3 = soff[3], o4 = soff[4];

#pragma unroll 1
    for (int pass = 0; pass < 8; pass++) {
        const int t0 = tq * 256 + pass * 32 + warp * 4;
        u64x S[4][4];
        u64x P[4], Q[4];
#pragma unroll
        for (int j = 0; j < 4; j++) P[j] = 0;

        // class 0: S_m += P
#pragma unroll 2
        for (int pos = o0; pos < o1; pos++) {
            int2 pf = sperm[pos];
            u64x A = sAd[pf.x * 32 + lane], B = sBd[pf.x * 32 + lane];
            int id = (pf.y * t0) & 4095;
#pragma unroll
            for (int j = 0; j < 4; j++) {
                ulonglong2 cs = ts2[id];
                P[j] = fma2(A, cs.x, P[j]);
                P[j] = fma2(B, cs.y, P[j]);
                id = (id + pf.y) & 4095;
            }
        }
#pragma unroll
        for (int j = 0; j < 4; j++) { S[0][j] = P[j]; S[1][j] = P[j]; S[2][j] = P[j]; S[3][j] = P[j]; }

        // class 1: S0+=P, S1+=Q, S2-=P, S3-=Q
#pragma unroll
        for (int j = 0; j < 4; j++) { P[j] = 0; Q[j] = 0; }
#pragma unroll 2
        for (int pos = o1; pos < o2; pos++) {
            int2 pf = sperm[pos];
            u64x A = sAd[pf.x * 32 + lane], B = sBd[pf.x * 32 + lane];
            u64x nA = neg2(A);
            int id = (pf.y * t0) & 4095;
#pragma unroll
            for (int j = 0; j < 4; j++) {
                ulonglong2 cs = ts2[id];
                P[j] = fma2(A, cs.x, P[j]);  P[j] = fma2(B, cs.y, P[j]);
                Q[j] = fma2(B, cs.x, Q[j]);  Q[j] = fma2(nA, cs.y, Q[j]);
                id = (id + pf.y) & 4095;
            }
        }
#pragma unroll
        for (int j = 0; j < 4; j++) {
            S[0][j] = add2(S[0][j], P[j]);  S[1][j] = add2(S[1][j], Q[j]);
            S[2][j] = sub2(S[2][j], P[j]);  S[3][j] = sub2(S[3][j], Q[j]);
        }

        // class 2: S0+=P, S1-=P, S2+=P, S3-=P
#pragma unroll
        for (int j = 0; j < 4; j++) P[j] = 0;
#pragma unroll 2
        for (int pos = o2; pos < o3; pos++) {
            int2 pf = sperm[pos];
            u64x A = sAd[pf.x * 32 + lane], B = sBd[pf.x * 32 + lane];
            int id = (pf.y * t0) & 4095;
#pragma unroll
            for (int j = 0; j < 4; j++) {
                ulonglong2 cs = ts2[id];
                P[j] = fma2(A, cs.x, P[j]);
                P[j] = fma2(B, cs.y, P[j]);
                id = (id + pf.y) & 4095;
            }
        }
#pragma unroll
        for (int j = 0; j < 4; j++) {
            S[0][j] = add2(S[0][j], P[j]);  S[1][j] = sub2(S[1][j], P[j]);
            S[2][j] = add2(S[2][j], P[j]);  S[3][j] = sub2(S[3][j], P[j]);
        }

        // class 3: S0+=P, S1-=Q, S2-=P, S3+=Q
#pragma unroll
        for (int j = 0; j < 4; j++) { P[j] = 0; Q[j] = 0; }
#pragma unroll 2
        for (int pos = o3; pos < o4; pos++) {
            int2 pf = sperm[pos];
            u64x A = sAd[pf.x * 32 + lane], B = sBd[pf.x * 32 + lane];
            u64x nA = neg2(A);
            int id = (pf.y * t0) & 4095;
#pragma unroll
            for (int j = 0; j < 4; j++) {
                ulonglong2 cs = ts2[id];
                P[j] = fma2(A, cs.x, P[j]);  P[j] = fma2(B, cs.y, P[j]);
                Q[j] = fma2(B, cs.x, Q[j]);  Q[j] = fma2(nA, cs.y, Q[j]);
                id = (id + pf.y) & 4095;
            }
        }
#pragma unroll
        for (int j = 0; j < 4; j++) {
            S[0][j] = add2(S[0][j], P[j]);  S[1][j] = sub2(S[1][j], Q[j]);
            S[2][j] = sub2(S[2][j], P[j]);  S[3][j] = add2(S[3][j], Q[j]);
        }

        // store 4 quadrants via smem transpose
#pragma unroll
        for (int m = 0; m < 4; m++) {
            __syncthreads();
#pragma unroll
            for (int j = 0; j < 4; j++) {
                float v0, v1;
                unpack2(S[m][j], v0, v1);
                int tl = warp * 4 + j;
                sT[(2 * lane) * 33 + tl]     = v0;
                sT[(2 * lane + 1) * 33 + tl] = v1;
            }
            __syncthreads();
            int tbase = m * 1024 + tq * 256 + pass * 32;
#pragma unroll
            for (int ii = 0; ii < 2; ii++) {
                int i = ii * 256 + tid;        // 512 float4
                int rr = i >> 3, c4 = i & 7;
                const float* sp = sT + rr * 33 + c4 * 4;
                float4 vv = make_float4(sp[0], sp[1], sp[2], sp[3]);
                *(float4*)&out[(size_t)(r0 + rr) * NL + tbase + c4 * 4] = vv;
            }
        }
    }
}

// ================= launch =================
extern "C" void kernel_launch(void* const* d_in, const int* in_sizes, int n_in,
                              void* d_out, int out_size) {
    const float* q  = (const float*)d_in[0];
    const float* k  = (const float*)d_in[1];
    // d_in[2] = v, never used by the reference
    const float* w1 = (const float*)d_in[3];
    const float* w2 = (const float*)d_in[4];
    const int* iq   = (const int*)d_in[5];
    const int* ikv  = (const int*)d_in[6];
    float* out = (float*)d_out;

    cudaFuncSetAttribute(k1_forward, cudaFuncAttributeMaxDynamicSharedMemorySize, K1_SMEM);
    cudaFuncSetAttribute(k2_middle,  cudaFuncAttributeMaxDynamicSharedMemorySize, K2_SMEM);
    cudaFuncSetAttribute(k3_inverse, cudaFuncAttributeMaxDynamicSharedMemorySize, K3_SMEM);

    k0_init<<<16, 256>>>();
    k1_forward<<<dim3(8, NB, 4), 256, K1_SMEM>>>(q, k, iq, ikv);
    k2_middle<<<dim3(NB * NH, 2), 256, K2_SMEM>>>(w1, w2, iq);
    k3_inverse<<<dim3(64, 4), 256, K3_SMEM>>>(out, iq);
}

// round 5
// speedup vs baseline: 1.1672x; 1.1672x over previous
#include <cuda_runtime.h>
#include <math.h>

#define NB 8
#define NL 4096
#define NH 8
#define NM 64
#define NCH 512

typedef unsigned long long u64x;

// ---------------- device scratch ----------------
__device__ ulonglong2 g_ts[4096];                  // (cc, ss) packed f32x2 of angle 2*pi*i/4096
__device__ float2 g_F[2 * 2 * NB * NM * NCH];      // [thalf][tensor][b][mode-pos][ch]
__device__ float2 g_O[NB * NH * 64 * NM];          // [row][mode-pos]: (A, B) pre-scaled

// ---------------- f32x2 helpers ----------------
static __device__ __forceinline__ u64x fma2(u64x a, u64x b, u64x c) {
    u64x d; asm("fma.rn.f32x2 %0,%1,%2,%3;" : "=l"(d) : "l"(a), "l"(b), "l"(c)); return d;
}
static __device__ __forceinline__ u64x add2(u64x a, u64x b) {
    u64x d; asm("add.rn.f32x2 %0,%1,%2;" : "=l"(d) : "l"(a), "l"(b)); return d;
}
#define NEG1X2 0xBF800000BF800000ULL
static __device__ __forceinline__ u64x sub2(u64x a, u64x b) { return fma2(b, NEG1X2, a); }
static __device__ __forceinline__ u64x neg2(u64x a) { return fma2(a, NEG1X2, 0ULL); }
static __device__ __forceinline__ void unpack2(u64x d, float& lo, float& hi) {
    asm("mov.b64 {%0,%1},%2;" : "=f"(lo), "=f"(hi) : "l"(d));
}

// ================= K0: trig table =================
__global__ void k0_init() {
    int i = blockIdx.x * 256 + threadIdx.x;
    if (i < 4096) {
        float s, c;
        sincospif((float)i / 2048.0f, &s, &c);
        u64x cc, ss;
        asm("mov.b64 %0,{%1,%1};" : "=l"(cc) : "f"(c));
        asm("mov.b64 %0,{%1,%1};" : "=l"(ss) : "f"(s));
        g_ts[i] = make_ulonglong2(cc, ss);
    }
}

// ================= K1: forward sparse DFT (radix-4, 8 modes/warp) =================
template<int CLS>
static __device__ __forceinline__ void k1_chunk(
    const u64x* __restrict__ xsd, const ulonglong2* __restrict__ ts2,
    int lane, u64x accR[8], u64x accS[8], int idx[8], const int F[8])
{
#pragma unroll 2
    for (int tt = 0; tt < 32; tt++) {
        u64x x0 = xsd[(0 * 32 + tt) * 32 + lane];
        u64x x1 = xsd[(1 * 32 + tt) * 32 + lane];
        u64x x2 = xsd[(2 * 32 + tt) * 32 + lane];
        u64x x3 = xsd[(3 * 32 + tt) * 32 + lane];
        u64x P, QR = 0, QS = 0;
        if (CLS == 0) {
            P = add2(add2(x0, x2), add2(x1, x3));
        } else if (CLS == 2) {
            P = sub2(add2(x0, x2), add2(x1, x3));
        } else {
            u64x bq = sub2(x0, x2);
            u64x d  = sub2(x1, x3);
            u64x nd = neg2(d);
            P  = bq;
            QR = (CLS == 1) ? nd : d;
            QS = (CLS == 1) ? d  : nd;
        }
#pragma unroll
        for (int k = 0; k < 8; k++) {
            ulonglong2 cs = ts2[idx[k]];
            accR[k] = fma2(P, cs.x, accR[k]);
            accS[k] = fma2(P, cs.y, accS[k]);
            if (CLS & 1) {
                accR[k] = fma2(QR, cs.y, accR[k]);
                accS[k] = fma2(QS, cs.x, accS[k]);
            }
            idx[k] = (idx[k] + F[k]) & 4095;
        }
    }
}

static __device__ __forceinline__ void k1_chunk_gen(
    const u64x* __restrict__ xsd, const ulonglong2* __restrict__ ts2,
    int lane, u64x accR[8], u64x accS[8], int chunk, const int F[8])
{
    for (int tt = 0; tt < 32; tt++) {
        int tp = chunk * 32 + tt;
#pragma unroll
        for (int m = 0; m < 4; m++) {
            u64x x = xsd[(m * 32 + tt) * 32 + lane];
            int tg = tp + 1024 * m;
#pragma unroll
            for (int k = 0; k < 8; k++) {
                int id = (F[k] * tg) & 4095;
                ulonglong2 cs = ts2[id];
                accR[k] = fma2(x, cs.x, accR[k]);
                accS[k] = fma2(x, cs.y, accS[k]);
            }
        }
    }
}

#define K1_SMEM (4096 * 16 + 4 * 32 * 64 * 4 + 256)
__global__ void __launch_bounds__(256, 2) k1_forward(const float* __restrict__ qp,
                                                     const float* __restrict__ kp,
                                                     const int* __restrict__ iq,
                                                     const int* __restrict__ ikv) {
    extern __shared__ char sm[];
    ulonglong2* ts2 = (ulonglong2*)sm;
    float* xs = (float*)(ts2 + 4096);            // [4 m][32 t'][64 ch]
    int* sMi = (int*)(xs + 4 * 32 * 64);         // [64] mode indices
    const u64x* xsd = (const u64x*)xs;

    const int ctile = blockIdx.x, b = blockIdx.y;
    const int tensor = blockIdx.z >> 1, thalf = blockIdx.z & 1;
    const float* src = tensor ? kp : qp;
    const int* idxarr = tensor ? ikv : iq;
    const int tid = threadIdx.x, lane = tid & 31, warp = tid >> 5;

    for (int i = tid; i < 4096; i += 256) ts2[i] = g_ts[i];

    // bucket 64 modes by class (F&3); warp w takes bucketed positions [8w, 8w+8)
    const unsigned FULL = 0xffffffffu;
    int Flo = idxarr[lane], Fhi = idxarr[lane + 32];
    int clo = Flo & 3, chi = Fhi & 3;
    unsigned mlo[4], mhi[4];
    int off[5]; off[0] = 0;
#pragma unroll
    for (int c = 0; c < 4; c++) {
        mlo[c] = __ballot_sync(FULL, clo == c);
        mhi[c] = __ballot_sync(FULL, chi == c);
    }
#pragma unroll
    for (int c = 0; c < 4; c++) off[c + 1] = off[c] + __popc(mlo[c]) + __popc(mhi[c]);
    unsigned lm = (1u << lane) - 1u;
    int p_lo = off[clo] + __popc(mlo[clo] & lm);
    int p_hi = off[chi] + __popc(mlo[chi]) + __popc(mhi[chi] & lm);
    int F[8];
#pragma unroll
    for (int k = 0; k < 8; k++) {
        int tpos = warp * 8 + k;
        unsigned ba = __ballot_sync(FULL, p_lo == tpos);
        unsigned bb = __ballot_sync(FULL, p_hi == tpos);
        int m = ba ? (__ffs(ba) - 1) : (32 + __ffs(bb) - 1);
        if (lane == 0) sMi[tpos] = m;
        F[k] = __shfl_sync(FULL, (m < 32) ? Flo : Fhi, m & 31);
    }
    int jcls = F[0] & 3;
    bool uni = true;
#pragma unroll
    for (int k = 1; k < 8; k++) uni = uni && ((F[k] & 3) == jcls);

    u64x accR[8], accS[8]; int idx[8];
#pragma unroll
    for (int k = 0; k < 8; k++) { accR[k] = 0; accS[k] = 0; }

    const float* base = src + (size_t)b * NL * NCH + ctile * 64;

    for (int cc = 0; cc < 16; cc++) {
        const int chunk = thalf * 16 + cc;
        __syncthreads();
#pragma unroll
        for (int ii = 0; ii < 8; ii++) {
            int i = ii * 256 + tid;                 // 2048 float4
            int c4 = i & 15, tt = (i >> 4) & 31, m = i >> 9;
            ((float4*)xs)[i] = *(const float4*)(base + (size_t)(chunk * 32 + tt + 1024 * m) * NCH + c4 * 4);
        }
        __syncthreads();
#pragma unroll
        for (int k = 0; k < 8; k++) idx[k] = (F[k] * (chunk * 32)) & 4095;
        if (uni) {
            switch (jcls) {
                case 0: k1_chunk<0>(xsd, ts2, lane, accR, accS, idx, F); break;
                case 1: k1_chunk<1>(xsd, ts2, lane, accR, accS, idx, F); break;
                case 2: k1_chunk<2>(xsd, ts2, lane, accR, accS, idx, F); break;
                default: k1_chunk<3>(xsd, ts2, lane, accR, accS, idx, F); break;
            }
        } else {
            k1_chunk_gen(xsd, ts2, lane, accR, accS, chunk, F);
        }
    }

    const int ch = ctile * 64 + lane * 2;
    float2* dst = g_F + ((size_t)((thalf * 2 + tensor) * NB + b) * NM) * NCH;
#pragma unroll
    for (int k = 0; k < 8; k++) {
        float r0, r1, s0, s1;
        unpack2(accR[k], r0, r1);
        unpack2(accS[k], s0, s1);
        int mi = sMi[warp * 8 + k];
        dst[(size_t)mi * NCH + ch]     = make_float2(r0, -s0);
        dst[(size_t)mi * NCH + ch + 1] = make_float2(r1, -s1);
    }
}

// ================= K2: per-(b,h) complex middle, quarter-x split =================
#define K2_SMEM (8192 + 33280 + 8704 + 8704)
__global__ void __launch_bounds__(256, 3) k2_middle(const float* __restrict__ w1,
                                                    const float* __restrict__ w2,
                                                    const int* __restrict__ iq) {
    extern __shared__ char sm[];
    float2* sFq  = (float2*)sm;              // [16 xl][64 e]
    float2* sFkT = sFq + 16 * 64;            // [64 e][65 y-pad]
    float2* sA   = sFkT + 64 * 65;           // [64 y][17 xl-pad]
    float2* sC   = sA + 64 * 17;             // [64 e][17 xl-pad]

    const int bh = blockIdx.x, b = bh >> 3, h = bh & 7;
    const int x0 = blockIdx.y * 16;
    const int tid = threadIdx.x;

    // load Fq slice (x quarter) and full Fk, summing the two t'-half partials
    for (int i = tid; i < 1024; i += 256) {
        int xl = i >> 6, e = i & 63;
        size_t o0 = ((size_t)(b) * NM + (x0 + xl)) * NCH + h * 64 + e;
        float2 a = g_F[o0], c = g_F[o0 + (size_t)2 * NB * NM * NCH];
        sFq[xl * 64 + e] = make_float2(a.x + c.x, a.y + c.y);
    }
    for (int i = tid; i < 4096; i += 256) {
        int e = i & 63, f = i >> 6;
        size_t o0 = ((size_t)(NB + b) * NM + f) * NCH + h * 64 + e;
        float2 a = g_F[o0], c = g_F[o0 + (size_t)2 * NB * NM * NCH];
        sFkT[e * 65 + f] = make_float2(a.x + c.x, a.y + c.y);
    }
    __syncthreads();

    // A[x][y] = tanh_c( sum_e Fq[e,x] * Fk[e,y] )
#pragma unroll 1
    for (int p = 0; p < 4; p++) {
        int i = p * 256 + tid, xl = i >> 6, y = i & 63;
        float re = 0.f, im = 0.f;
#pragma unroll 4
        for (int e = 0; e < 64; e++) {
            float2 a = sFq[xl * 64 + e];    // broadcast
            float2 c = sFkT[e * 65 + y];    // consecutive
            re += a.x * c.x - a.y * c.y;
            im += a.x * c.y + a.y * c.x;
        }
        sA[y * 17 + xl] = make_float2(tanhf(re), tanhf(im));
    }
    __syncthreads();

    // C[e][x] = sum_y A[x,y] * Fk[e,y]
#pragma unroll 1
    for (int p = 0; p < 4; p++) {
        int i = p * 256 + tid, xl = i & 15, e = i >> 4;
        float re = 0.f, im = 0.f;
#pragma unroll 4
        for (int y = 0; y < 64; y++) {
            float2 a  = sA[y * 17 + xl];    // consecutive
            float2 kv = sFkT[e * 65 + y];   // broadcast
            re += a.x * kv.x - a.y * kv.y;
            im += a.x * kv.y + a.y * kv.x;
        }
        sC[e * 17 + xl] = make_float2(re, im);
    }
    __syncthreads();

    // O[o][x] = sum_e C[e,x] * (w1 + i w2)[h,e,o,x]; pre-scale for irfft
#pragma unroll 1
    for (int p = 0; p < 4; p++) {
        int i = p * 256 + tid, xl = i & 15, o = i >> 4, x = x0 + xl;
        float re = 0.f, im = 0.f;
        size_t wbase = (((size_t)h * 64) * 64 + o) * 64 + x;
#pragma unroll 4
        for (int e = 0; e < 64; e++) {
            float2 c = sC[e * 17 + xl];
            float wr = w1[wbase + (size_t)e * 4096];
            float wi = w2[wbase + (size_t)e * 4096];
            re += c.x * wr - c.y * wi;
            im += c.x * wi + c.y * wr;
        }
        int fx = iq[x];
        float s = ((fx == 0) || (fx == NL / 2) ? 1.0f : 2.0f) * 9.313225746154785e-10f; // 2^-30
        int row = (b * 8 + h) * 64 + o;
        g_O[(size_t)row * NM + x] = make_float2(s * re, -s * im);
    }
}

// ================= K3: inverse sparse DFT (radix-4, 8 t/warp, 4-acc regroup) =================
// S0 = (P0+P2)+O, S2 = (P0+P2)-O, S1 = (P0-P2)+R, S3 = (P0-P2)-R
// where O = P1+P3, R = Q1-Q3;  P = A cc + B ss, Q = B cc - A ss
#define K3_SMEM (4096*16 + 4096*4*2 + 64*65*4 + 64*8 + 32)
__global__ void __launch_bounds__(256, 2) k3_inverse(float* __restrict__ out,
                                                     const int* __restrict__ iq) {
    extern __shared__ char sm[];
    ulonglong2* ts2 = (ulonglong2*)sm;            // 64KB
    float* sA = (float*)(ts2 + 4096);             // [pos][64 rows]
    float* sB = sA + 4096;
    float* sT = sB + 4096;                        // [64 rows][65]
    int2* sperm = (int2*)(sT + 64 * 65);          // bucketed pos -> (orig pos, freq)
    int* soff = (int*)(sperm + 64);               // class offsets [5]

    const int rt = blockIdx.x;                    // 64 row tiles
    const int tq = blockIdx.y;                    // 4 t' quarters
    const int r0 = rt * 64;
    const int tid = threadIdx.x, lane = tid & 31, warp = tid >> 5;

    for (int i = tid; i < 4096; i += 256) ts2[i] = g_ts[i];
    for (int i = tid; i < 4096; i += 256) {
        int f = i >> 6, rr = i & 63;
        float2 v = g_O[(size_t)(r0 + rr) * NM + f];
        sA[f * 64 + rr] = v.x;
        sB[f * 64 + rr] = v.y;
    }
    if (warp == 0) {
        const unsigned FULL = 0xffffffffu;
        int Flo = iq[lane], Fhi = iq[lane + 32];
        int clo = Flo & 3, chi = Fhi & 3;
        unsigned mlo[4], mhi[4];
        int off[5]; off[0] = 0;
#pragma unroll
        for (int c = 0; c < 4; c++) {
            mlo[c] = __ballot_sync(FULL, clo == c);
            mhi[c] = __ballot_sync(FULL, chi == c);
        }
#pragma unroll
        for (int c = 0; c < 4; c++) off[c + 1] = off[c] + __popc(mlo[c]) + __popc(mhi[c]);
        unsigned lmm = (1u << lane) - 1u;
        int p_lo = off[clo] + __popc(mlo[clo] & lmm);
        int p_hi = off[chi] + __popc(mlo[chi]) + __popc(mhi[chi] & lmm);
        sperm[p_lo] = make_int2(lane, Flo);
        sperm[p_hi] = make_int2(lane + 32, Fhi);
        if (lane < 5) soff[lane] = off[lane];
    }
    __syncthreads();

    const u64x* sAd = (const u64x*)sA;
    const u64x* sBd = (const u64x*)sB;
    const int o0 = soff[0], o1 = soff[1], o2 = soff[2], o3 = soff[3], o4 = soff[4];

#pragma unroll 1
    for (int pass = 0; pass < 4; pass++) {
        const int t0 = tq * 256 + pass * 64 + warp * 8;
        u64x P0[8], P2[8], O[8], R[8];
#pragma unroll
        for (int j = 0; j < 8; j++) { P0[j] = 0; P2[j] = 0; O[j] = 0; R[j] = 0; }

        // class 0 -> P0
#pragma unroll 2
        for (int pos = o0; pos < o1; pos++) {
            int2 pf = sperm[pos];
            u64x A = sAd[pf.x * 32 + lane], B = sBd[pf.x * 32 + lane];
            int id = (pf.y * t0) & 4095;
#pragma unroll
            for (int j = 0; j < 8; j++) {
                ulonglong2 cs = ts2[id];
                P0[j] = fma2(A, cs.x, P0[j]);
                P0[j] = fma2(B, cs.y, P0[j]);
                id = (id + pf.y) & 4095;
            }
        }
        // class 1 -> O += P, R += Q  (Q = B cc - A ss)
#pragma unroll 2
        for (int pos = o1; pos < o2; pos++) {
            int2 pf = sperm[pos];
            u64x A = sAd[pf.x * 32 + lane], B = sBd[pf.x * 32 + lane];
            u64x nA = neg2(A);
            int id = (pf.y * t0) & 4095;
#pragma unroll
            for (int j = 0; j < 8; j++) {
                ulonglong2 cs = ts2[id];
                O[j] = fma2(A, cs.x, O[j]);   O[j] = fma2(B, cs.y, O[j]);
                R[j] = fma2(B, cs.x, R[j]);   R[j] = fma2(nA, cs.y, R[j]);
                id = (id + pf.y) & 4095;
            }
        }
        // class 2 -> P2
#pragma unroll 2
        for (int pos = o2; pos < o3; pos++) {
            int2 pf = sperm[pos];
            u64x A = sAd[pf.x * 32 + lane], B = sBd[pf.x * 32 + lane];
            int id = (pf.y * t0) & 4095;
#pragma unroll
            for (int j = 0; j < 8; j++) {
                ulonglong2 cs = ts2[id];
                P2[j] = fma2(A, cs.x, P2[j]);
                P2[j] = fma2(B, cs.y, P2[j]);
                id = (id + pf.y) & 4095;
            }
        }
        // class 3 -> O += P, R -= Q  (-Q = (-B) cc + A ss)
#pragma unroll 2
        for (int pos = o3; pos < o4; pos++) {
            int2 pf = sperm[pos];
            u64x A = sAd[pf.x * 32 + lane], B = sBd[pf.x * 32 + lane];
            u64x nB = neg2(B);
            int id = (pf.y * t0) & 4095;
#pragma unroll
            for (int j = 0; j < 8; j++) {
                ulonglong2 cs = ts2[id];
                O[j] = fma2(A, cs.x, O[j]);   O[j] = fma2(B, cs.y, O[j]);
                R[j] = fma2(nB, cs.x, R[j]);  R[j] = fma2(A, cs.y, R[j]);
                id = (id + pf.y) & 4095;
            }
        }

        // reconstruct 4 quadrants and store via smem transpose
#pragma unroll 1
        for (int m = 0; m < 4; m++) {
            __syncthreads();
#pragma unroll
            for (int j = 0; j < 8; j++) {
                u64x S;
                if (m == 0)      S = add2(add2(P0[j], P2[j]), O[j]);
                else if (m == 1) S = add2(sub2(P0[j], P2[j]), R[j]);
                else if (m == 2) S = sub2(add2(P0[j], P2[j]), O[j]);
                else             S = sub2(sub2(P0[j], P2[j]), R[j]);
                float v0, v1;
                unpack2(S, v0, v1);
                int tl = warp * 8 + j;
                sT[(2 * lane) * 65 + tl]     = v0;
                sT[(2 * lane + 1) * 65 + tl] = v1;
            }
            __syncthreads();
            int tbase = m * 1024 + tq * 256 + pass * 64;
#pragma unroll
            for (int ii = 0; ii < 4; ii++) {
                int i = ii * 256 + tid;        // 1024 float4
                int rr = i >> 4, c4 = i & 15;
                const float* sp = sT + rr * 65 + c4 * 4;
                float4 vv = make_float4(sp[0], sp[1], sp[2], sp[3]);
                *(float4*)&out[(size_t)(r0 + rr) * NL + tbase + c4 * 4] = vv;
            }
        }
    }
}

// ================= launch =================
extern "C" void kernel_launch(void* const* d_in, const int* in_sizes, int n_in,
                              void* d_out, int out_size) {
    const float* q  = (const float*)d_in[0];
    const float* k  = (const float*)d_in[1];
    // d_in[2] = v, never used by the reference
    const float* w1 = (const float*)d_in[3];
    const float* w2 = (const float*)d_in[4];
    const int* iq   = (const int*)d_in[5];
    const int* ikv  = (const int*)d_in[6];
    float* out = (float*)d_out;

    cudaFuncSetAttribute(k1_forward, cudaFuncAttributeMaxDynamicSharedMemorySize, K1_SMEM);
    cudaFuncSetAttribute(k2_middle,  cudaFuncAttributeMaxDynamicSharedMemorySize, K2_SMEM);
    cudaFuncSetAttribute(k3_inverse, cudaFuncAttributeMaxDynamicSharedMemorySize, K3_SMEM);

    k0_init<<<16, 256>>>();
    k1_forward<<<dim3(8, NB, 4), 256, K1_SMEM>>>(q, k, iq, ikv);
    k2_middle<<<dim3(NB * NH, 4), 256, K2_SMEM>>>(w1, w2, iq);
    k3_inverse<<<dim3(64, 4), 256, K3_SMEM>>>(out, iq);
}

// round 6
// speedup vs baseline: 1.2400x; 1.0624x over previous
#include <cuda_runtime.h>
#include <math.h>

#define NB 8
#define NL 4096
#define NH 8
#define NM 64
#define NCH 512

typedef unsigned long long u64x;

// ---------------- device scratch ----------------
__device__ ulonglong2 g_ts[4096];                  // (cc, ss) packed f32x2 of angle 2*pi*i/4096
__device__ float2 g_F[8 * NB * NM * NCH];          // [tq*2+tensor][b][mode-pos][ch]
__device__ float2 g_O[NB * NH * 64 * NM];          // [row][mode-pos]: (A, B) pre-scaled

// ---------------- f32x2 helpers ----------------
static __device__ __forceinline__ u64x fma2(u64x a, u64x b, u64x c) {
    u64x d; asm("fma.rn.f32x2 %0,%1,%2,%3;" : "=l"(d) : "l"(a), "l"(b), "l"(c)); return d;
}
static __device__ __forceinline__ u64x add2(u64x a, u64x b) {
    u64x d; asm("add.rn.f32x2 %0,%1,%2;" : "=l"(d) : "l"(a), "l"(b)); return d;
}
#define NEG1X2 0xBF800000BF800000ULL
static __device__ __forceinline__ u64x sub2(u64x a, u64x b) { return fma2(b, NEG1X2, a); }
static __device__ __forceinline__ u64x neg2(u64x a) { return fma2(a, NEG1X2, 0ULL); }
static __device__ __forceinline__ void unpack2(u64x d, float& lo, float& hi) {
    asm("mov.b64 {%0,%1},%2;" : "=f"(lo), "=f"(hi) : "l"(d));
}

// ================= K0: trig table =================
__global__ void k0_init() {
    int i = blockIdx.x * 256 + threadIdx.x;
    if (i < 4096) {
        float s, c;
        sincospif((float)i / 2048.0f, &s, &c);
        u64x cc, ss;
        asm("mov.b64 %0,{%1,%1};" : "=l"(cc) : "f"(c));
        asm("mov.b64 %0,{%1,%1};" : "=l"(ss) : "f"(s));
        g_ts[i] = make_ulonglong2(cc, ss);
    }
}

// ================= K1: forward sparse DFT (radix-4, 8 modes/warp, 4 ch/lane) =================
template<int CLS>
static __device__ __forceinline__ void k1_chunk(
    const ulonglong2* __restrict__ xs2, const ulonglong2* __restrict__ ts2,
    int lane, u64x accR[16], u64x accS[16], int idx[8], const int F[8])
{
#pragma unroll 2
    for (int tt = 0; tt < 16; tt++) {
        ulonglong2 x0 = xs2[(0 * 16 + tt) * 32 + lane];
        ulonglong2 x1 = xs2[(1 * 16 + tt) * 32 + lane];
        ulonglong2 x2 = xs2[(2 * 16 + tt) * 32 + lane];
        ulonglong2 x3 = xs2[(3 * 16 + tt) * 32 + lane];
        u64x P[2], QR[2], QS[2];
        if (CLS == 0) {
            P[0] = add2(add2(x0.x, x2.x), add2(x1.x, x3.x));
            P[1] = add2(add2(x0.y, x2.y), add2(x1.y, x3.y));
        } else if (CLS == 2) {
            P[0] = sub2(add2(x0.x, x2.x), add2(x1.x, x3.x));
            P[1] = sub2(add2(x0.y, x2.y), add2(x1.y, x3.y));
        } else {
#pragma unroll
            for (int p = 0; p < 2; p++) {
                u64x a0 = p ? x0.y : x0.x, a2 = p ? x2.y : x2.x;
                u64x a1 = p ? x1.y : x1.x, a3 = p ? x3.y : x3.x;
                u64x bq = sub2(a0, a2);
                u64x d  = sub2(a1, a3);
                u64x nd = neg2(d);
                P[p]  = bq;
                QR[p] = (CLS == 1) ? nd : d;
                QS[p] = (CLS == 1) ? d  : nd;
            }
        }
#pragma unroll
        for (int k = 0; k < 8; k++) {
            ulonglong2 cs = ts2[idx[k]];
#pragma unroll
            for (int p = 0; p < 2; p++) {
                accR[k * 2 + p] = fma2(P[p], cs.x, accR[k * 2 + p]);
                accS[k * 2 + p] = fma2(P[p], cs.y, accS[k * 2 + p]);
                if (CLS & 1) {
                    accR[k * 2 + p] = fma2(QR[p], cs.y, accR[k * 2 + p]);
                    accS[k * 2 + p] = fma2(QS[p], cs.x, accS[k * 2 + p]);
                }
            }
            idx[k] = (idx[k] + F[k]) & 4095;
        }
    }
}

static __device__ __forceinline__ void k1_chunk_gen(
    const ulonglong2* __restrict__ xs2, const ulonglong2* __restrict__ ts2,
    int lane, u64x accR[16], u64x accS[16], int tp0, const int F[8])
{
    for (int tt = 0; tt < 16; tt++) {
#pragma unroll
        for (int m = 0; m < 4; m++) {
            ulonglong2 x = xs2[(m * 16 + tt) * 32 + lane];
            int tg = tp0 + tt + 1024 * m;
#pragma unroll
            for (int k = 0; k < 8; k++) {
                int id = (F[k] * tg) & 4095;
                ulonglong2 cs = ts2[id];
                accR[k * 2 + 0] = fma2(x.x, cs.x, accR[k * 2 + 0]);
                accS[k * 2 + 0] = fma2(x.x, cs.y, accS[k * 2 + 0]);
                accR[k * 2 + 1] = fma2(x.y, cs.x, accR[k * 2 + 1]);
                accS[k * 2 + 1] = fma2(x.y, cs.y, accS[k * 2 + 1]);
            }
        }
    }
}

#define K1_SMEM (4096 * 16 + 4 * 16 * 128 * 4 + 256)
__global__ void __launch_bounds__(256, 2) k1_forward(const float* __restrict__ qp,
                                                     const float* __restrict__ kp,
                                                     const int* __restrict__ iq,
                                                     const int* __restrict__ ikv) {
    extern __shared__ char sm[];
    ulonglong2* ts2 = (ulonglong2*)sm;
    float* xs = (float*)(ts2 + 4096);            // [4 m][16 t'][128 ch]
    int* sMi = (int*)(xs + 4 * 16 * 128);        // [64]
    const ulonglong2* xs2 = (const ulonglong2*)xs;

    const int ctile = blockIdx.x, b = blockIdx.y;
    const int tensor = blockIdx.z >> 2, tq = blockIdx.z & 3;
    const float* src = tensor ? kp : qp;
    const int* idxarr = tensor ? ikv : iq;
    const int tid = threadIdx.x, lane = tid & 31, warp = tid >> 5;

    for (int i = tid; i < 4096; i += 256) ts2[i] = g_ts[i];

    // bucket 64 modes by class (F&3); warp w takes bucketed positions [8w, 8w+8)
    const unsigned FULL = 0xffffffffu;
    int Flo = idxarr[lane], Fhi = idxarr[lane + 32];
    int clo = Flo & 3, chi = Fhi & 3;
    unsigned mlo[4], mhi[4];
    int off[5]; off[0] = 0;
#pragma unroll
    for (int c = 0; c < 4; c++) {
        mlo[c] = __ballot_sync(FULL, clo == c);
        mhi[c] = __ballot_sync(FULL, chi == c);
    }
#pragma unroll
    for (int c = 0; c < 4; c++) off[c + 1] = off[c] + __popc(mlo[c]) + __popc(mhi[c]);
    unsigned lm = (1u << lane) - 1u;
    int p_lo = off[clo] + __popc(mlo[clo] & lm);
    int p_hi = off[chi] + __popc(mlo[chi]) + __popc(mhi[chi] & lm);
    int F[8];
#pragma unroll
    for (int k = 0; k < 8; k++) {
        int tpos = warp * 8 + k;
        unsigned ba = __ballot_sync(FULL, p_lo == tpos);
        unsigned bb = __ballot_sync(FULL, p_hi == tpos);
        int m = ba ? (__ffs(ba) - 1) : (32 + __ffs(bb) - 1);
        if (lane == 0) sMi[tpos] = m;
        F[k] = __shfl_sync(FULL, (m < 32) ? Flo : Fhi, m & 31);
    }
    int jcls = F[0] & 3;
    bool uni = true;
#pragma unroll
    for (int k = 1; k < 8; k++) uni = uni && ((F[k] & 3) == jcls);

    u64x accR[16], accS[16]; int idx[8];
#pragma unroll
    for (int k = 0; k < 16; k++) { accR[k] = 0; accS[k] = 0; }

    const float* base = src + (size_t)b * NL * NCH + ctile * 128;

    for (int cc = 0; cc < 16; cc++) {
        const int tp0 = tq * 256 + cc * 16;
        __syncthreads();
#pragma unroll
        for (int ii = 0; ii < 8; ii++) {
            int i = ii * 256 + tid;                 // 2048 float4
            int c4 = i & 31, tt = (i >> 5) & 15, m = i >> 9;
            ((float4*)xs)[i] = *(const float4*)(base + (size_t)(tp0 + tt + 1024 * m) * NCH + c4 * 4);
        }
        __syncthreads();
#pragma unroll
        for (int k = 0; k < 8; k++) idx[k] = (F[k] * tp0) & 4095;
        if (uni) {
            switch (jcls) {
                case 0: k1_chunk<0>(xs2, ts2, lane, accR, accS, idx, F); break;
                case 1: k1_chunk<1>(xs2, ts2, lane, accR, accS, idx, F); break;
                case 2: k1_chunk<2>(xs2, ts2, lane, accR, accS, idx, F); break;
                default: k1_chunk<3>(xs2, ts2, lane, accR, accS, idx, F); break;
            }
        } else {
            k1_chunk_gen(xs2, ts2, lane, accR, accS, tp0, F);
        }
    }

    const int ch = ctile * 128 + lane * 4;
    float2* dst = g_F + ((size_t)((tq * 2 + tensor) * NB + b) * NM) * NCH;
#pragma unroll
    for (int k = 0; k < 8; k++) {
        float r0, r1, r2, r3, s0, s1, s2, s3;
        unpack2(accR[k * 2 + 0], r0, r1);
        unpack2(accS[k * 2 + 0], s0, s1);
        unpack2(accR[k * 2 + 1], r2, r3);
        unpack2(accS[k * 2 + 1], s2, s3);
        int mi = sMi[warp * 8 + k];
        float2* dp = &dst[(size_t)mi * NCH + ch];
        *(float4*)(dp)     = make_float4(r0, -s0, r1, -s1);
        *(float4*)(dp + 2) = make_float4(r2, -s2, r3, -s3);
    }
}

// ================= K2: per-(b,h) complex middle, quarter-x split =================
#define K2_SMEM (8192 + 33280 + 8704 + 8704)
__global__ void __launch_bounds__(256, 3) k2_middle(const float* __restrict__ w1,
                                                    const float* __restrict__ w2,
                                                    const int* __restrict__ iq) {
    extern __shared__ char sm[];
    float2* sFq  = (float2*)sm;              // [16 xl][64 e]
    float2* sFkT = sFq + 16 * 64;            // [64 e][65 y-pad]
    float2* sA   = sFkT + 64 * 65;           // [64 y][17 xl-pad]
    float2* sC   = sA + 64 * 17;             // [64 e][17 xl-pad]

    const int bh = blockIdx.x, b = bh >> 3, h = bh & 7;
    const int x0 = blockIdx.y * 16;
    const int tid = threadIdx.x;
    const size_t QSTR = (size_t)2 * NB * NM * NCH;

    for (int i = tid; i < 1024; i += 256) {
        int xl = i >> 6, e = i & 63;
        size_t o0 = ((size_t)(b) * NM + (x0 + xl)) * NCH + h * 64 + e;
        float2 a0 = g_F[o0], a1 = g_F[o0 + QSTR], a2 = g_F[o0 + 2 * QSTR], a3 = g_F[o0 + 3 * QSTR];
        sFq[xl * 64 + e] = make_float2(a0.x + a1.x + a2.x + a3.x, a0.y + a1.y + a2.y + a3.y);
    }
    for (int i = tid; i < 4096; i += 256) {
        int e = i & 63, f = i >> 6;
        size_t o0 = ((size_t)(NB + b) * NM + f) * NCH + h * 64 + e;
        float2 a0 = g_F[o0], a1 = g_F[o0 + QSTR], a2 = g_F[o0 + 2 * QSTR], a3 = g_F[o0 + 3 * QSTR];
        sFkT[e * 65 + f] = make_float2(a0.x + a1.x + a2.x + a3.x, a0.y + a1.y + a2.y + a3.y);
    }
    __syncthreads();

    // A[x][y] = tanh_c( sum_e Fq[e,x] * Fk[e,y] )
#pragma unroll 1
    for (int p = 0; p < 4; p++) {
        int i = p * 256 + tid, xl = i >> 6, y = i & 63;
        float re = 0.f, im = 0.f;
#pragma unroll 4
        for (int e = 0; e < 64; e++) {
            float2 a = sFq[xl * 64 + e];
            float2 c = sFkT[e * 65 + y];
            re += a.x * c.x - a.y * c.y;
            im += a.x * c.y + a.y * c.x;
        }
        sA[y * 17 + xl] = make_float2(tanhf(re), tanhf(im));
    }
    __syncthreads();

    // C[e][x] = sum_y A[x,y] * Fk[e,y]
#pragma unroll 1
    for (int p = 0; p < 4; p++) {
        int i = p * 256 + tid, xl = i & 15, e = i >> 4;
        float re = 0.f, im = 0.f;
#pragma unroll 4
        for (int y = 0; y < 64; y++) {
            float2 a  = sA[y * 17 + xl];
            float2 kv = sFkT[e * 65 + y];
            re += a.x * kv.x - a.y * kv.y;
            im += a.x * kv.y + a.y * kv.x;
        }
        sC[e * 17 + xl] = make_float2(re, im);
    }
    __syncthreads();

    // O[o][x] = sum_e C[e,x] * (w1 + i w2)[h,e,o,x]; pre-scale for irfft
#pragma unroll 1
    for (int p = 0; p < 4; p++) {
        int i = p * 256 + tid, xl = i & 15, o = i >> 4, x = x0 + xl;
        float re = 0.f, im = 0.f;
        size_t wbase = (((size_t)h * 64) * 64 + o) * 64 + x;
#pragma unroll 4
        for (int e = 0; e < 64; e++) {
            float2 c = sC[e * 17 + xl];
            float wr = w1[wbase + (size_t)e * 4096];
            float wi = w2[wbase + (size_t)e * 4096];
            re += c.x * wr - c.y * wi;
            im += c.x * wi + c.y * wr;
        }
        int fx = iq[x];
        float s = ((fx == 0) || (fx == NL / 2) ? 1.0f : 2.0f) * 9.313225746154785e-10f; // 2^-30
        int row = (b * 8 + h) * 64 + o;
        g_O[(size_t)row * NM + x] = make_float2(s * re, -s * im);
    }
}

// ================= K3: inverse sparse DFT (radix-4, 128 rows/CTA, 4 rows/lane) =================
// S0 = (P0+P2)+O, S2 = (P0+P2)-O, S1 = (P0-P2)+R, S3 = (P0-P2)-R
// O = P1+P3, R = Q1-Q3;  P = A cc + B ss, Q = B cc - A ss
#define K3_SMEM (4096 * 16 + 32768 + 32768 + 128 * 65 * 4 + 64 * 8 + 64)
__global__ void __launch_bounds__(512, 1) k3_inverse(float* __restrict__ out,
                                                     const int* __restrict__ iq) {
    extern __shared__ char sm[];
    ulonglong2* ts2 = (ulonglong2*)sm;            // 64KB
    float* sA = (float*)(ts2 + 4096);             // [f][128 slots]
    float* sB = sA + 64 * 128;
    float* sT = sB + 64 * 128;                    // [128 rows][65]
    int2* sperm = (int2*)(sT + 128 * 65);
    int* soff = (int*)(sperm + 64);

    const int rt = blockIdx.x;                    // 32 row tiles of 128
    const int tq = blockIdx.y;                    // 4 t' quarters
    const int r0 = rt * 128;
    const int tid = threadIdx.x, lane = tid & 31, warp = tid >> 5;

    for (int i = tid; i < 4096; i += 512) ts2[i] = g_ts[i];
    // load g_O: slot layout so one LDS.128 per f gives rows (2l,2l+1,64+2l,64+2l+1)
    for (int i = tid; i < 8192; i += 512) {
        int rr = i >> 6, f = i & 63;
        float2 v = g_O[(size_t)(r0 + rr) * NM + f];
        int half = rr >> 6, pr = (rr & 63) >> 1, sl = half * 2 + (rr & 1);
        sA[f * 128 + pr * 4 + sl] = v.x;
        sB[f * 128 + pr * 4 + sl] = v.y;
    }
    if (warp == 0) {
        const unsigned FULL = 0xffffffffu;
        int Flo = iq[lane], Fhi = iq[lane + 32];
        int clo = Flo & 3, chi = Fhi & 3;
        unsigned mlo[4], mhi[4];
        int off[5]; off[0] = 0;
#pragma unroll
        for (int c = 0; c < 4; c++) {
            mlo[c] = __ballot_sync(FULL, clo == c);
            mhi[c] = __ballot_sync(FULL, chi == c);
        }
#pragma unroll
        for (int c = 0; c < 4; c++) off[c + 1] = off[c] + __popc(mlo[c]) + __popc(mhi[c]);
        unsigned lmm = (1u << lane) - 1u;
        int p_lo = off[clo] + __popc(mlo[clo] & lmm);
        int p_hi = off[chi] + __popc(mlo[chi]) + __popc(mhi[chi] & lmm);
        sperm[p_lo] = make_int2(lane, Flo);
        sperm[p_hi] = make_int2(lane + 32, Fhi);
        if (lane < 5) soff[lane] = off[lane];
    }
    __syncthreads();

    const ulonglong2* sAd = (const ulonglong2*)sA;   // 32 ulonglong2 per f
    const ulonglong2* sBd = (const ulonglong2*)sB;
    const int o0 = soff[0], o1 = soff[1], o2 = soff[2], o3 = soff[3], o4 = soff[4];

#pragma unroll 1
    for (int pass = 0; pass < 4; pass++) {
        const int t0 = tq * 256 + pass * 64 + warp * 4;
        u64x P0[8], P2[8], O[8], R[8];   // [j*2 + pack]
#pragma unroll
        for (int j = 0; j < 8; j++) { P0[j] = 0; P2[j] = 0; O[j] = 0; R[j] = 0; }

        // class 0 -> P0
#pragma unroll 2
        for (int pos = o0; pos < o1; pos++) {
            int2 pf = sperm[pos];
            ulonglong2 A = sAd[pf.x * 32 + lane], B = sBd[pf.x * 32 + lane];
            int id = (pf.y * t0) & 4095;
#pragma unroll
            for (int j = 0; j < 4; j++) {
                ulonglong2 cs = ts2[id];
                P0[j * 2 + 0] = fma2(A.x, cs.x, P0[j * 2 + 0]);  P0[j * 2 + 0] = fma2(B.x, cs.y, P0[j * 2 + 0]);
                P0[j * 2 + 1] = fma2(A.y, cs.x, P0[j * 2 + 1]);  P0[j * 2 + 1] = fma2(B.y, cs.y, P0[j * 2 + 1]);
                id = (id + pf.y) & 4095;
            }
        }
        // class 1 -> O += P, R += Q
#pragma unroll 2
        for (int pos = o1; pos < o2; pos++) {
            int2 pf = sperm[pos];
            ulonglong2 A = sAd[pf.x * 32 + lane], B = sBd[pf.x * 32 + lane];
            u64x nAx = neg2(A.x), nAy = neg2(A.y);
            int id = (pf.y * t0) & 4095;
#pragma unroll
            for (int j = 0; j < 4; j++) {
                ulonglong2 cs = ts2[id];
                O[j * 2 + 0] = fma2(A.x, cs.x, O[j * 2 + 0]);   O[j * 2 + 0] = fma2(B.x, cs.y, O[j * 2 + 0]);
                O[j * 2 + 1] = fma2(A.y, cs.x, O[j * 2 + 1]);   O[j * 2 + 1] = fma2(B.y, cs.y, O[j * 2 + 1]);
                R[j * 2 + 0] = fma2(B.x, cs.x, R[j * 2 + 0]);   R[j * 2 + 0] = fma2(nAx, cs.y, R[j * 2 + 0]);
                R[j * 2 + 1] = fma2(B.y, cs.x, R[j * 2 + 1]);   R[j * 2 + 1] = fma2(nAy, cs.y, R[j * 2 + 1]);
                id = (id + pf.y) & 4095;
            }
        }
        // class 2 -> P2
#pragma unroll 2
        for (int pos = o2; pos < o3; pos++) {
            int2 pf = sperm[pos];
            ulonglong2 A = sAd[pf.x * 32 + lane], B = sBd[pf.x * 32 + lane];
            int id = (pf.y * t0) & 4095;
#pragma unroll
            for (int j = 0; j < 4; j++) {
                ulonglong2 cs = ts2[id];
                P2[j * 2 + 0] = fma2(A.x, cs.x, P2[j * 2 + 0]);  P2[j * 2 + 0] = fma2(B.x, cs.y, P2[j * 2 + 0]);
                P2[j * 2 + 1] = fma2(A.y, cs.x, P2[j * 2 + 1]);  P2[j * 2 + 1] = fma2(B.y, cs.y, P2[j * 2 + 1]);
                id = (id + pf.y) & 4095;
            }
        }
        // class 3 -> O += P, R -= Q
#pragma unroll 2
        for (int pos = o3; pos < o4; pos++) {
            int2 pf = sperm[pos];
            ulonglong2 A = sAd[pf.x * 32 + lane], B = sBd[pf.x * 32 + lane];
            u64x nBx = neg2(B.x), nBy = neg2(B.y);
            int id = (pf.y * t0) & 4095;
#pragma unroll
            for (int j = 0; j < 4; j++) {
                ulonglong2 cs = ts2[id];
                O[j * 2 + 0] = fma2(A.x, cs.x, O[j * 2 + 0]);   O[j * 2 + 0] = fma2(B.x, cs.y, O[j * 2 + 0]);
                O[j * 2 + 1] = fma2(A.y, cs.x, O[j * 2 + 1]);   O[j * 2 + 1] = fma2(B.y, cs.y, O[j * 2 + 1]);
                R[j * 2 + 0] = fma2(nBx, cs.x, R[j * 2 + 0]);   R[j * 2 + 0] = fma2(A.x, cs.y, R[j * 2 + 0]);
                R[j * 2 + 1] = fma2(nBy, cs.x, R[j * 2 + 1]);   R[j * 2 + 1] = fma2(A.y, cs.y, R[j * 2 + 1]);
                id = (id + pf.y) & 4095;
            }
        }

        // reconstruct 4 quadrants, transpose through sT, store
#pragma unroll 1
        for (int m = 0; m < 4; m++) {
            __syncthreads();
#pragma unroll
            for (int j = 0; j < 4; j++) {
#pragma unroll
                for (int p = 0; p < 2; p++) {
                    u64x S;
                    u64x Ps = add2(P0[j * 2 + p], P2[j * 2 + p]);
                    u64x Pd = sub2(P0[j * 2 + p], P2[j * 2 + p]);
                    if (m == 0)      S = add2(Ps, O[j * 2 + p]);
                    else if (m == 1) S = add2(Pd, R[j * 2 + p]);
                    else if (m == 2) S = sub2(Ps, O[j * 2 + p]);
                    else             S = sub2(Pd, R[j * 2 + p]);
                    float v0, v1;
                    unpack2(S, v0, v1);
                    int tl = warp * 4 + j;
                    int rbase = p * 64 + 2 * lane;
                    sT[rbase * 65 + tl]       = v0;
                    sT[(rbase + 1) * 65 + tl] = v1;
                }
            }
            __syncthreads();
            int tbase = m * 1024 + tq * 256 + pass * 64;
#pragma unroll
            for (int ii = 0; ii < 4; ii++) {
                int i = ii * 512 + tid;        // 2048 float4
                int rr = i >> 4, c4 = i & 15;
                const float* sp = sT + rr * 65 + c4 * 4;
                float4 vv = make_float4(sp[0], sp[1], sp[2], sp[3]);
                *(float4*)&out[(size_t)(r0 + rr) * NL + tbase + c4 * 4] = vv;
            }
        }
    }
}

// ================= launch =================
extern "C" void kernel_launch(void* const* d_in, const int* in_sizes, int n_in,
                              void* d_out, int out_size) {
    const float* q  = (const float*)d_in[0];
    const float* k  = (const float*)d_in[1];
    // d_in[2] = v, never used by the reference
    const float* w1 = (const float*)d_in[3];
    const float* w2 = (const float*)d_in[4];
    const int* iq   = (const int*)d_in[5];
    const int* ikv  = (const int*)d_in[6];
    float* out = (float*)d_out;

    cudaFuncSetAttribute(k1_forward, cudaFuncAttributeMaxDynamicSharedMemorySize, K1_SMEM);
    cudaFuncSetAttribute(k2_middle,  cudaFuncAttributeMaxDynamicSharedMemorySize, K2_SMEM);
    cudaFuncSetAttribute(k3_inverse, cudaFuncAttributeMaxDynamicSharedMemorySize, K3_SMEM);

    k0_init<<<16, 256>>>();
    k1_forward<<<dim3(4, NB, 8), 256, K1_SMEM>>>(q, k, iq, ikv);
    k2_middle<<<dim3(NB * NH, 4), 256, K2_SMEM>>>(w1, w2, iq);
    k3_inverse<<<dim3(32, 4), 512, K3_SMEM>>>(out, iq);
}